// round 1
// baseline (speedup 1.0000x reference)
#include <cuda_runtime.h>
#include <math.h>

#define N_B   32
#define C_IN  128
#define L_LEN 512
#define C_P   64
#define P_NUM 2000
#define P_PAD 2048
#define N_CLS 200
#define EPS   1e-4f

// Scratch (no cudaMalloc allowed)
__device__ float g_h[N_B * C_P * L_LEN];       // 4 MB  relu(conv1)
__device__ float g_f[N_B * C_P * L_LEN];       // 4 MB  sigmoid(conv2)
__device__ float g_protoT[C_P * P_PAD];        // 512 KB  proto^T, zero-padded P
__device__ float g_p2[P_PAD];                  // ||proto||^2, zero-padded
__device__ float g_w1t[C_IN * C_P];            // W1^T [c][o]
__device__ float g_w2t[C_P * C_P];             // W2^T [c][o]
__device__ float g_act[N_B * P_NUM];           // prototype activations

// ---------------------------------------------------------------------------
// Prep: transposes + prototype norms (tiny)
// ---------------------------------------------------------------------------
__global__ void prep_kernel(const float* __restrict__ W1,
                            const float* __restrict__ W2,
                            const float* __restrict__ proto) {
    int stride = gridDim.x * blockDim.x;
    int tid = blockIdx.x * blockDim.x + threadIdx.x;
    for (int e = tid; e < C_IN * C_P; e += stride) {
        int c = e >> 6, o = e & 63;
        g_w1t[e] = W1[o * C_IN + c];
    }
    for (int e = tid; e < C_P * C_P; e += stride) {
        int c = e >> 6, o = e & 63;
        g_w2t[e] = W2[o * C_P + c];
    }
    for (int e = tid; e < C_P * P_PAD; e += stride) {
        int k = e >> 11, p = e & (P_PAD - 1);
        g_protoT[e] = (p < P_NUM) ? proto[p * C_P + k] : 0.f;
    }
    for (int p = tid; p < P_PAD; p += stride) {
        float s = 0.f;
        if (p < P_NUM) {
            #pragma unroll 8
            for (int c = 0; c < C_P; c++) {
                float v = proto[p * C_P + c];
                s += v * v;
            }
        }
        g_p2[p] = s;
    }
}

// ---------------------------------------------------------------------------
// conv1: h = relu(W1 @ x[n] + b1)   per-n GEMM  64x512, K=128
// grid (L/32, N), 256 threads (16 l-threads x 16 o-threads), 4o x 2l micro-tile
// ---------------------------------------------------------------------------
__global__ void __launch_bounds__(256) conv1_kernel(const float* __restrict__ x,
                                                    const float* __restrict__ b1) {
    __shared__ float xs[C_IN][32];    // 16 KB
    __shared__ float w1s[C_IN][C_P];  // 32 KB
    int n  = blockIdx.y;
    int l0 = blockIdx.x * 32;
    int tid = threadIdx.x;

    for (int e = tid; e < C_IN * 32; e += 256) {
        int c = e >> 5, l = e & 31;
        xs[c][l] = x[(n * C_IN + c) * L_LEN + l0 + l];
    }
    for (int e = tid; e < C_IN * C_P; e += 256)
        w1s[e >> 6][e & 63] = g_w1t[e];
    __syncthreads();

    int tl = tid & 15, to = tid >> 4;
    float acc[4][2] = {};
    #pragma unroll
    for (int k = 0; k < C_IN; k++) {
        float4 a = *(const float4*)&w1s[k][to * 4];
        float2 b = *(const float2*)&xs[k][tl * 2];
        acc[0][0] += a.x * b.x; acc[0][1] += a.x * b.y;
        acc[1][0] += a.y * b.x; acc[1][1] += a.y * b.y;
        acc[2][0] += a.z * b.x; acc[2][1] += a.z * b.y;
        acc[3][0] += a.w * b.x; acc[3][1] += a.w * b.y;
    }
    float4 bv = *(const float4*)&b1[to * 4];
    float bb[4] = {bv.x, bv.y, bv.z, bv.w};
    #pragma unroll
    for (int i = 0; i < 4; i++) {
        int o = to * 4 + i;
        float2 hv;
        hv.x = fmaxf(acc[i][0] + bb[i], 0.f);
        hv.y = fmaxf(acc[i][1] + bb[i], 0.f);
        *(float2*)&g_h[(n * C_P + o) * L_LEN + l0 + tl * 2] = hv;
    }
}

// ---------------------------------------------------------------------------
// conv2: f = sigmoid(W2 @ h[n] + b2)   64x512, K=64
// ---------------------------------------------------------------------------
__global__ void __launch_bounds__(256) conv2_kernel(const float* __restrict__ b2) {
    __shared__ float hs[C_P][32];    // 8 KB
    __shared__ float w2s[C_P][C_P];  // 16 KB
    int n  = blockIdx.y;
    int l0 = blockIdx.x * 32;
    int tid = threadIdx.x;

    for (int e = tid; e < C_P * 32; e += 256) {
        int c = e >> 5, l = e & 31;
        hs[c][l] = g_h[(n * C_P + c) * L_LEN + l0 + l];
    }
    for (int e = tid; e < C_P * C_P; e += 256)
        w2s[e >> 6][e & 63] = g_w2t[e];
    __syncthreads();

    int tl = tid & 15, to = tid >> 4;
    float acc[4][2] = {};
    #pragma unroll
    for (int k = 0; k < C_P; k++) {
        float4 a = *(const float4*)&w2s[k][to * 4];
        float2 b = *(const float2*)&hs[k][tl * 2];
        acc[0][0] += a.x * b.x; acc[0][1] += a.x * b.y;
        acc[1][0] += a.y * b.x; acc[1][1] += a.y * b.y;
        acc[2][0] += a.z * b.x; acc[2][1] += a.z * b.y;
        acc[3][0] += a.w * b.x; acc[3][1] += a.w * b.y;
    }
    float4 bv = *(const float4*)&b2[to * 4];
    float bb[4] = {bv.x, bv.y, bv.z, bv.w};
    #pragma unroll
    for (int i = 0; i < 4; i++) {
        int o = to * 4 + i;
        float2 fv;
        float z0 = acc[i][0] + bb[i];
        float z1 = acc[i][1] + bb[i];
        fv.x = 1.f / (1.f + __expf(-z0));
        fv.y = 1.f / (1.f + __expf(-z1));
        *(float2*)&g_f[(n * C_P + o) * L_LEN + l0 + tl * 2] = fv;
    }
}

// ---------------------------------------------------------------------------
// Main kernel: fused  xp GEMM + distance + relu + min over L + log activation
// grid (P_PAD/64 = 32, N = 32), 256 threads (16 tx=l, 16 ty=p), 4x4 micro-tile
// ---------------------------------------------------------------------------
__global__ void __launch_bounds__(256) l2min_kernel(float* __restrict__ mind_out) {
    __shared__ float as_[C_P][64];   // proto tile [k][p]   16 KB
    __shared__ float bs[C_P][64];    // f tile     [k][l]   16 KB
    __shared__ float x2p[4][64];     // partial sum-of-squares per l

    int n  = blockIdx.y;
    int pt = blockIdx.x;
    int tid = threadIdx.x;
    int tx = tid & 15, ty = tid >> 4;

    for (int e = tid; e < C_P * 64; e += 256) {
        int k = e >> 6, p = e & 63;
        as_[k][p] = g_protoT[k * P_PAD + pt * 64 + p];
    }
    float p2v[4];
    #pragma unroll
    for (int i = 0; i < 4; i++)
        p2v[i] = g_p2[pt * 64 + ty * 4 + i];

    float mind[4] = {1e30f, 1e30f, 1e30f, 1e30f};

    for (int lc = 0; lc < L_LEN / 64; lc++) {
        __syncthreads();  // protect bs reuse from previous chunk
        for (int e = tid; e < C_P * 64; e += 256) {
            int k = e >> 6, l = e & 63;
            bs[k][l] = g_f[(n * C_P + k) * L_LEN + lc * 64 + l];
        }
        __syncthreads();

        {   // x2 partials: 4 groups of 16 k-rows
            int r = tid >> 6, l = tid & 63;
            float s = 0.f;
            #pragma unroll
            for (int k = 0; k < 16; k++) {
                float v = bs[r * 16 + k][l];
                s += v * v;
            }
            x2p[r][l] = s;
        }
        __syncthreads();

        float acc[4][4] = {};
        #pragma unroll
        for (int k = 0; k < C_P; k++) {
            float4 a = *(const float4*)&as_[k][ty * 4];
            float4 b = *(const float4*)&bs[k][tx * 4];
            acc[0][0] += a.x * b.x; acc[0][1] += a.x * b.y; acc[0][2] += a.x * b.z; acc[0][3] += a.x * b.w;
            acc[1][0] += a.y * b.x; acc[1][1] += a.y * b.y; acc[1][2] += a.y * b.z; acc[1][3] += a.y * b.w;
            acc[2][0] += a.z * b.x; acc[2][1] += a.z * b.y; acc[2][2] += a.z * b.z; acc[2][3] += a.z * b.w;
            acc[3][0] += a.w * b.x; acc[3][1] += a.w * b.y; acc[3][2] += a.w * b.z; acc[3][3] += a.w * b.w;
        }

        float x2v[4];
        #pragma unroll
        for (int j = 0; j < 4; j++) {
            int l = tx * 4 + j;
            x2v[j] = x2p[0][l] + x2p[1][l] + x2p[2][l] + x2p[3][l];
        }
        #pragma unroll
        for (int i = 0; i < 4; i++) {
            #pragma unroll
            for (int j = 0; j < 4; j++) {
                float d = fmaxf(x2v[j] - 2.f * acc[i][j] + p2v[i], 0.f);
                mind[i] = fminf(mind[i], d);
            }
        }
    }

    // min across the 16 tx lanes (same ty group == aligned 16-lane shfl groups)
    #pragma unroll
    for (int i = 0; i < 4; i++) {
        float v = mind[i];
        #pragma unroll
        for (int off = 8; off > 0; off >>= 1)
            v = fminf(v, __shfl_xor_sync(0xffffffffu, v, off, 16));
        if (tx == 0) {
            int p = pt * 64 + ty * 4 + i;
            if (p < P_NUM) {
                if (mind_out) mind_out[n * P_NUM + p] = v;
                g_act[n * P_NUM + p] = logf((v + 1.f) / (v + EPS));
            }
        }
    }
}

// ---------------------------------------------------------------------------
// logits[n][c] = sum_p act[n][p] * last_w[c][p]
// grid (N_CLS, N_B), 64 threads; fixed-order reduction -> deterministic
// ---------------------------------------------------------------------------
__global__ void logits_kernel(const float* __restrict__ lw, float* __restrict__ out) {
    int c = blockIdx.x, n = blockIdx.y;
    int tid = threadIdx.x;
    const float* a = &g_act[n * P_NUM];
    const float* w = &lw[c * P_NUM];
    float s = 0.f;
    for (int j = tid; j < P_NUM; j += 64)
        s += a[j] * w[j];
    #pragma unroll
    for (int off = 16; off > 0; off >>= 1)
        s += __shfl_xor_sync(0xffffffffu, s, off);
    __shared__ float red[2];
    if ((tid & 31) == 0) red[tid >> 5] = s;
    __syncthreads();
    if (tid == 0) out[n * N_CLS + c] = red[0] + red[1];
}

// ---------------------------------------------------------------------------
extern "C" void kernel_launch(void* const* d_in, const int* in_sizes, int n_in,
                              void* d_out, int out_size) {
    const float* x     = (const float*)d_in[0];
    const float* W1    = (const float*)d_in[1];
    const float* b1    = (const float*)d_in[2];
    const float* W2    = (const float*)d_in[3];
    const float* b2    = (const float*)d_in[4];
    const float* proto = (const float*)d_in[5];
    const float* lw    = (const float*)d_in[6];
    float* out = (float*)d_out;

    // Output layout: [logits (32*200) | min_distances (32*2000)]
    float* mind_out = (out_size >= N_B * N_CLS + N_B * P_NUM)
                          ? out + N_B * N_CLS : nullptr;

    prep_kernel<<<256, 256>>>(W1, W2, proto);
    conv1_kernel<<<dim3(L_LEN / 32, N_B), 256>>>(x, b1);
    conv2_kernel<<<dim3(L_LEN / 32, N_B), 256>>>(b2);
    l2min_kernel<<<dim3(P_PAD / 64, N_B), 256>>>(mind_out);
    logits_kernel<<<dim3(N_CLS, N_B), 64>>>(lw, out);
}

// round 2
// speedup vs baseline: 1.1346x; 1.1346x over previous
#include <cuda_runtime.h>
#include <math.h>

#define N_B   32
#define C_IN  128
#define L_LEN 512
#define C_P   64
#define P_NUM 2000
#define P_PAD 2048
#define N_CLS 200
#define EPS   1e-4f

typedef unsigned long long ull;

// Scratch (no cudaMalloc allowed)
__device__ float g_h[N_B * C_P * L_LEN];       // relu(conv1)
__device__ float g_f[N_B * C_P * L_LEN];       // sigmoid(conv2)
__device__ float g_protoT[C_P * P_PAD];        // proto^T [k][p], zero-padded P
__device__ float g_p2[P_PAD];                  // ||proto||^2
__device__ float g_w1t[C_IN * C_P];            // W1^T [c][o]
__device__ float g_w2t[C_P * C_P];             // W2^T [c][o]
__device__ float g_act[N_B * P_NUM];           // prototype activations

// ---- packed f32x2 helpers ------------------------------------------------
__device__ __forceinline__ ull pack2(float lo, float hi) {
    ull r;
    asm("mov.b64 %0, {%1, %2};" : "=l"(r) : "f"(lo), "f"(hi));
    return r;
}
__device__ __forceinline__ void unpack2(ull v, float &lo, float &hi) {
    asm("mov.b64 {%0, %1}, %2;" : "=f"(lo), "=f"(hi) : "l"(v));
}
__device__ __forceinline__ void ffma2(ull &d, ull a, ull b) {
    asm("fma.rn.f32x2 %0, %1, %2, %0;" : "+l"(d) : "l"(a), "l"(b));
}

// ---------------------------------------------------------------------------
// Prep: transposes + prototype norms (tiny)
// ---------------------------------------------------------------------------
__global__ void prep_kernel(const float* __restrict__ W1,
                            const float* __restrict__ W2,
                            const float* __restrict__ proto) {
    int stride = gridDim.x * blockDim.x;
    int tid = blockIdx.x * blockDim.x + threadIdx.x;
    for (int e = tid; e < C_IN * C_P; e += stride) {
        int c = e >> 6, o = e & 63;
        g_w1t[e] = W1[o * C_IN + c];
    }
    for (int e = tid; e < C_P * C_P; e += stride) {
        int c = e >> 6, o = e & 63;
        g_w2t[e] = W2[o * C_P + c];
    }
    for (int e = tid; e < C_P * P_PAD; e += stride) {
        int k = e >> 11, p = e & (P_PAD - 1);
        g_protoT[e] = (p < P_NUM) ? proto[p * C_P + k] : 0.f;
    }
    for (int p = tid; p < P_PAD; p += stride) {
        float s = 0.f;
        if (p < P_NUM) {
            #pragma unroll 8
            for (int c = 0; c < C_P; c++) {
                float v = proto[p * C_P + c];
                s += v * v;
            }
        }
        g_p2[p] = s;
    }
}

// ---------------------------------------------------------------------------
// conv1: h = relu(W1 @ x[n] + b1)   per-n GEMM  64x512, K=128
// ---------------------------------------------------------------------------
__global__ void __launch_bounds__(256) conv1_kernel(const float* __restrict__ x,
                                                    const float* __restrict__ b1) {
    __shared__ float xs[C_IN][32];
    __shared__ float w1s[C_IN][C_P];
    int n  = blockIdx.y;
    int l0 = blockIdx.x * 32;
    int tid = threadIdx.x;

    for (int e = tid; e < C_IN * 32; e += 256) {
        int c = e >> 5, l = e & 31;
        xs[c][l] = x[(n * C_IN + c) * L_LEN + l0 + l];
    }
    for (int e = tid; e < C_IN * C_P; e += 256)
        w1s[e >> 6][e & 63] = g_w1t[e];
    __syncthreads();

    int tl = tid & 15, to = tid >> 4;
    float acc[4][2] = {};
    #pragma unroll
    for (int k = 0; k < C_IN; k++) {
        float4 a = *(const float4*)&w1s[k][to * 4];
        float2 b = *(const float2*)&xs[k][tl * 2];
        acc[0][0] += a.x * b.x; acc[0][1] += a.x * b.y;
        acc[1][0] += a.y * b.x; acc[1][1] += a.y * b.y;
        acc[2][0] += a.z * b.x; acc[2][1] += a.z * b.y;
        acc[3][0] += a.w * b.x; acc[3][1] += a.w * b.y;
    }
    float4 bv = *(const float4*)&b1[to * 4];
    float bb[4] = {bv.x, bv.y, bv.z, bv.w};
    #pragma unroll
    for (int i = 0; i < 4; i++) {
        int o = to * 4 + i;
        float2 hv;
        hv.x = fmaxf(acc[i][0] + bb[i], 0.f);
        hv.y = fmaxf(acc[i][1] + bb[i], 0.f);
        *(float2*)&g_h[(n * C_P + o) * L_LEN + l0 + tl * 2] = hv;
    }
}

// ---------------------------------------------------------------------------
// conv2: f = sigmoid(W2 @ h[n] + b2)   64x512, K=64
// ---------------------------------------------------------------------------
__global__ void __launch_bounds__(256) conv2_kernel(const float* __restrict__ b2) {
    __shared__ float hs[C_P][32];
    __shared__ float w2s[C_P][C_P];
    int n  = blockIdx.y;
    int l0 = blockIdx.x * 32;
    int tid = threadIdx.x;

    for (int e = tid; e < C_P * 32; e += 256) {
        int c = e >> 5, l = e & 31;
        hs[c][l] = g_h[(n * C_P + c) * L_LEN + l0 + l];
    }
    for (int e = tid; e < C_P * C_P; e += 256)
        w2s[e >> 6][e & 63] = g_w2t[e];
    __syncthreads();

    int tl = tid & 15, to = tid >> 4;
    float acc[4][2] = {};
    #pragma unroll
    for (int k = 0; k < C_P; k++) {
        float4 a = *(const float4*)&w2s[k][to * 4];
        float2 b = *(const float2*)&hs[k][tl * 2];
        acc[0][0] += a.x * b.x; acc[0][1] += a.x * b.y;
        acc[1][0] += a.y * b.x; acc[1][1] += a.y * b.y;
        acc[2][0] += a.z * b.x; acc[2][1] += a.z * b.y;
        acc[3][0] += a.w * b.x; acc[3][1] += a.w * b.y;
    }
    float4 bv = *(const float4*)&b2[to * 4];
    float bb[4] = {bv.x, bv.y, bv.z, bv.w};
    #pragma unroll
    for (int i = 0; i < 4; i++) {
        int o = to * 4 + i;
        float2 fv;
        float z0 = acc[i][0] + bb[i];
        float z1 = acc[i][1] + bb[i];
        fv.x = 1.f / (1.f + __expf(-z0));
        fv.y = 1.f / (1.f + __expf(-z1));
        *(float2*)&g_f[(n * C_P + o) * L_LEN + l0 + tl * 2] = fv;
    }
}

// ---------------------------------------------------------------------------
// Main kernel: fused xp GEMM (packed f32x2 FFMA) + distance + min + log act
// grid (P_PAD/128 = 16, N = 32), 256 threads (tx 16 = l, ty 16 = p), 8x8 tile
// Dynamic SMEM: as_[64][128] | bs[64][128] | x2p[2][128] | p2s[128]
// ---------------------------------------------------------------------------
__global__ void __launch_bounds__(256, 2) l2min_kernel(float* __restrict__ mind_out) {
    extern __shared__ float sm[];
    float (*as_)[128] = (float (*)[128])sm;             // 32 KB
    float (*bs)[128]  = (float (*)[128])(sm + 8192);    // 32 KB
    float* x2p = sm + 16384;                            // 2*128
    float* p2s = sm + 16640;                            // 128

    int n  = blockIdx.y;
    int pt = blockIdx.x;
    int tid = threadIdx.x;
    int tx = tid & 15, ty = tid >> 4;

    // proto tile [k][p] (float4 loads)
    for (int e = tid; e < C_P * 32; e += 256) {
        int k = e >> 5, p4 = e & 31;
        ((float4*)&as_[k][0])[p4] =
            *(const float4*)&g_protoT[k * P_PAD + pt * 128 + p4 * 4];
    }
    if (tid < 128) p2s[tid] = g_p2[pt * 128 + tid];

    float mind[8];
    #pragma unroll
    for (int i = 0; i < 8; i++) mind[i] = 1e30f;

    for (int lc = 0; lc < L_LEN / 128; lc++) {
        __syncthreads();  // guard bs/x2p overwrite vs previous epilogue reads
        for (int e = tid; e < C_P * 32; e += 256) {
            int k = e >> 5, l4 = e & 31;
            ((float4*)&bs[k][0])[l4] =
                *(const float4*)&g_f[(n * C_P + k) * L_LEN + lc * 128 + l4 * 4];
        }
        __syncthreads();
        {   // per-l sum of squares, split over two 32-row halves
            int r = tid >> 7, l = tid & 127;
            float s = 0.f;
            #pragma unroll
            for (int k = 0; k < 32; k++) {
                float v = bs[r * 32 + k][l];
                s = fmaf(v, v, s);
            }
            x2p[r * 128 + l] = s;
        }
        __syncthreads();

        ull acc[8][4];
        #pragma unroll
        for (int i = 0; i < 8; i++)
            #pragma unroll
            for (int j = 0; j < 4; j++) acc[i][j] = 0ull;

        #pragma unroll 4
        for (int k = 0; k < C_P; k++) {
            ulonglong2 b01 = *(const ulonglong2*)&bs[k][tx * 8];
            ulonglong2 b23 = *(const ulonglong2*)&bs[k][tx * 8 + 4];
            float4 a0 = *(const float4*)&as_[k][ty * 8];
            float4 a1 = *(const float4*)&as_[k][ty * 8 + 4];
            ull ad[8];
            ad[0] = pack2(a0.x, a0.x); ad[1] = pack2(a0.y, a0.y);
            ad[2] = pack2(a0.z, a0.z); ad[3] = pack2(a0.w, a0.w);
            ad[4] = pack2(a1.x, a1.x); ad[5] = pack2(a1.y, a1.y);
            ad[6] = pack2(a1.z, a1.z); ad[7] = pack2(a1.w, a1.w);
            #pragma unroll
            for (int i = 0; i < 8; i++) {
                ffma2(acc[i][0], ad[i], b01.x);
                ffma2(acc[i][1], ad[i], b01.y);
                ffma2(acc[i][2], ad[i], b23.x);
                ffma2(acc[i][3], ad[i], b23.y);
            }
        }

        // epilogue: d = relu(x2 - 2*xp + p2), fold min over this l-chunk
        float x2v[8];
        #pragma unroll
        for (int j = 0; j < 8; j++) {
            int l = tx * 8 + j;
            x2v[j] = x2p[l] + x2p[128 + l];
        }
        #pragma unroll
        for (int i = 0; i < 8; i++) {
            float p2v = p2s[ty * 8 + i];
            #pragma unroll
            for (int jp = 0; jp < 4; jp++) {
                float lo, hi;
                unpack2(acc[i][jp], lo, hi);
                float d0 = fmaxf(fmaf(-2.f, lo, x2v[jp * 2])     + p2v, 0.f);
                float d1 = fmaxf(fmaf(-2.f, hi, x2v[jp * 2 + 1]) + p2v, 0.f);
                mind[i] = fminf(mind[i], fminf(d0, d1));
            }
        }
    }

    // min across the 16 tx lanes (aligned 16-lane shuffle groups)
    #pragma unroll
    for (int i = 0; i < 8; i++) {
        float v = mind[i];
        #pragma unroll
        for (int off = 8; off > 0; off >>= 1)
            v = fminf(v, __shfl_xor_sync(0xffffffffu, v, off, 16));
        if (tx == 0) {
            int p = pt * 128 + ty * 8 + i;
            if (p < P_NUM) {
                if (mind_out) mind_out[n * P_NUM + p] = v;
                g_act[n * P_NUM + p] = logf((v + 1.f) / (v + EPS));
            }
        }
    }
}

// ---------------------------------------------------------------------------
// logits[n][c] = sum_p act[n][p] * last_w[c][p]
// ---------------------------------------------------------------------------
__global__ void logits_kernel(const float* __restrict__ lw, float* __restrict__ out) {
    int c = blockIdx.x, n = blockIdx.y;
    int tid = threadIdx.x;
    const float* a = &g_act[n * P_NUM];
    const float* w = &lw[c * P_NUM];
    float s = 0.f;
    for (int j = tid; j < P_NUM; j += 64)
        s += a[j] * w[j];
    #pragma unroll
    for (int off = 16; off > 0; off >>= 1)
        s += __shfl_xor_sync(0xffffffffu, s, off);
    __shared__ float red[2];
    if ((tid & 31) == 0) red[tid >> 5] = s;
    __syncthreads();
    if (tid == 0) out[n * N_CLS + c] = red[0] + red[1];
}

// ---------------------------------------------------------------------------
extern "C" void kernel_launch(void* const* d_in, const int* in_sizes, int n_in,
                              void* d_out, int out_size) {
    const float* x     = (const float*)d_in[0];
    const float* W1    = (const float*)d_in[1];
    const float* b1    = (const float*)d_in[2];
    const float* W2    = (const float*)d_in[3];
    const float* b2    = (const float*)d_in[4];
    const float* proto = (const float*)d_in[5];
    const float* lw    = (const float*)d_in[6];
    float* out = (float*)d_out;

    float* mind_out = (out_size >= N_B * N_CLS + N_B * P_NUM)
                          ? out + N_B * N_CLS : nullptr;

    const int l2min_smem = (8192 + 8192 + 256 + 128) * sizeof(float);  // 67072 B
    cudaFuncSetAttribute(l2min_kernel,
                         cudaFuncAttributeMaxDynamicSharedMemorySize, l2min_smem);

    prep_kernel<<<256, 256>>>(W1, W2, proto);
    conv1_kernel<<<dim3(L_LEN / 32, N_B), 256>>>(x, b1);
    conv2_kernel<<<dim3(L_LEN / 32, N_B), 256>>>(b2);
    l2min_kernel<<<dim3(P_PAD / 128, N_B), 256, l2min_smem>>>(mind_out);
    logits_kernel<<<dim3(N_CLS, N_B), 64>>>(lw, out);
}

// round 4
// speedup vs baseline: 1.4174x; 1.2493x over previous
#include <cuda_runtime.h>
#include <cuda_fp16.h>
#include <cstdint>
#include <math.h>

#define N_B   32
#define C_IN  128
#define L_LEN 512
#define C_P   64
#define P_NUM 2000
#define P_PAD 2048
#define N_CLS 200
#define EPS   1e-4f

// ---------------- scratch (no cudaMalloc allowed) --------------------------
__device__ float g_h[N_B * C_P * L_LEN];     // relu(conv1)
__device__ float g_f[N_B * C_P * L_LEN];     // sigmoid(conv2)  [n][k][l]
__device__ float g_p2[P_PAD];                // ||proto||^2
__device__ float g_x2[N_B * L_LEN];          // per-position sum f^2
__device__ float g_w1t[C_IN * C_P];          // W1^T
__device__ float g_w2t[C_P * C_P];           // W2^T
__device__ float g_act[N_B * P_NUM];         // prototype activations
// fp16 split operands, K-major rows of 64 halves = 128B = 8 uint4
__device__ uint4 g_ph[P_PAD * 8];            // proto hi  [p][k]
__device__ uint4 g_pl[P_PAD * 8];            // proto lo
__device__ uint4 g_fh[N_B * L_LEN * 8];      // f hi      [n*l][k]
__device__ uint4 g_fl[N_B * L_LEN * 8];      // f lo

// ---------------- helpers ---------------------------------------------------
__device__ __forceinline__ uint32_t smem_u32(const void* p) {
    uint32_t a;
    asm("{ .reg .u64 t; cvta.to.shared.u64 t, %1; cvt.u32.u64 %0, t; }"
        : "=r"(a) : "l"(p));
    return a;
}
__device__ __forceinline__ void ldmx4(uint32_t* r, uint32_t addr) {
    asm volatile("ldmatrix.sync.aligned.m8n8.x4.shared.b16 {%0,%1,%2,%3}, [%4];"
                 : "=r"(r[0]), "=r"(r[1]), "=r"(r[2]), "=r"(r[3]) : "r"(addr));
}
__device__ __forceinline__ void mma16816(float* c, const uint32_t* a, const uint32_t* b) {
    asm volatile("mma.sync.aligned.m16n8k16.row.col.f32.f16.f16.f32 "
                 "{%0,%1,%2,%3}, {%4,%5,%6,%7}, {%8,%9}, {%0,%1,%2,%3};"
                 : "+f"(c[0]), "+f"(c[1]), "+f"(c[2]), "+f"(c[3])
                 : "r"(a[0]), "r"(a[1]), "r"(a[2]), "r"(a[3]), "r"(b[0]), "r"(b[1]));
}
__device__ __forceinline__ uint32_t pack_half2(float v0, float v1) {
    __half h0 = __float2half_rn(v0), h1 = __float2half_rn(v1);
    return (uint32_t)__half_as_ushort(h0) | ((uint32_t)__half_as_ushort(h1) << 16);
}

// ---------------------------------------------------------------------------
// Prep: transposes, proto norms, proto fp16 hi/lo split
// ---------------------------------------------------------------------------
__global__ void prep_kernel(const float* __restrict__ W1,
                            const float* __restrict__ W2,
                            const float* __restrict__ proto) {
    int stride = gridDim.x * blockDim.x;
    int tid = blockIdx.x * blockDim.x + threadIdx.x;
    for (int e = tid; e < C_IN * C_P; e += stride) {
        int c = e >> 6, o = e & 63;
        g_w1t[e] = W1[o * C_IN + c];
    }
    for (int e = tid; e < C_P * C_P; e += stride) {
        int c = e >> 6, o = e & 63;
        g_w2t[e] = W2[o * C_P + c];
    }
    for (int p = tid; p < P_PAD; p += stride) {
        float s = 0.f;
        if (p < P_NUM) {
            #pragma unroll 8
            for (int c = 0; c < C_P; c++) {
                float v = proto[p * C_P + c];
                s += v * v;
            }
        }
        g_p2[p] = s;
    }
    for (int e = tid; e < P_PAD * 8; e += stride) {
        int p = e >> 3, u = e & 7;
        uint32_t hw[4], lw[4];
        #pragma unroll
        for (int j = 0; j < 4; j++) {
            float v0 = 0.f, v1 = 0.f;
            if (p < P_NUM) {
                v0 = proto[p * C_P + u * 8 + j * 2];
                v1 = proto[p * C_P + u * 8 + j * 2 + 1];
            }
            __half h0 = __float2half_rn(v0), h1 = __float2half_rn(v1);
            float r0 = v0 - __half2float(h0), r1 = v1 - __half2float(h1);
            hw[j] = (uint32_t)__half_as_ushort(h0) | ((uint32_t)__half_as_ushort(h1) << 16);
            lw[j] = pack_half2(r0, r1);
        }
        g_ph[e] = make_uint4(hw[0], hw[1], hw[2], hw[3]);
        g_pl[e] = make_uint4(lw[0], lw[1], lw[2], lw[3]);
    }
}

// ---------------------------------------------------------------------------
// conv1: h = relu(W1 @ x[n] + b1)
// ---------------------------------------------------------------------------
__global__ void __launch_bounds__(256) conv1_kernel(const float* __restrict__ x,
                                                    const float* __restrict__ b1) {
    __shared__ float xs[C_IN][32];
    __shared__ float w1s[C_IN][C_P];
    int n  = blockIdx.y;
    int l0 = blockIdx.x * 32;
    int tid = threadIdx.x;

    for (int e = tid; e < C_IN * 32; e += 256) {
        int c = e >> 5, l = e & 31;
        xs[c][l] = x[(n * C_IN + c) * L_LEN + l0 + l];
    }
    for (int e = tid; e < C_IN * C_P; e += 256)
        w1s[e >> 6][e & 63] = g_w1t[e];
    __syncthreads();

    int tl = tid & 15, to = tid >> 4;
    float acc[4][2] = {};
    #pragma unroll
    for (int k = 0; k < C_IN; k++) {
        float4 a = *(const float4*)&w1s[k][to * 4];
        float2 b = *(const float2*)&xs[k][tl * 2];
        acc[0][0] += a.x * b.x; acc[0][1] += a.x * b.y;
        acc[1][0] += a.y * b.x; acc[1][1] += a.y * b.y;
        acc[2][0] += a.z * b.x; acc[2][1] += a.z * b.y;
        acc[3][0] += a.w * b.x; acc[3][1] += a.w * b.y;
    }
    float4 bv = *(const float4*)&b1[to * 4];
    float bb[4] = {bv.x, bv.y, bv.z, bv.w};
    #pragma unroll
    for (int i = 0; i < 4; i++) {
        int o = to * 4 + i;
        float2 hv;
        hv.x = fmaxf(acc[i][0] + bb[i], 0.f);
        hv.y = fmaxf(acc[i][1] + bb[i], 0.f);
        *(float2*)&g_h[(n * C_P + o) * L_LEN + l0 + tl * 2] = hv;
    }
}

// ---------------------------------------------------------------------------
// conv2: f = sigmoid(W2 @ h[n] + b2)
// ---------------------------------------------------------------------------
__global__ void __launch_bounds__(256) conv2_kernel(const float* __restrict__ b2) {
    __shared__ float hs[C_P][32];
    __shared__ float w2s[C_P][C_P];
    int n  = blockIdx.y;
    int l0 = blockIdx.x * 32;
    int tid = threadIdx.x;

    for (int e = tid; e < C_P * 32; e += 256) {
        int c = e >> 5, l = e & 31;
        hs[c][l] = g_h[(n * C_P + c) * L_LEN + l0 + l];
    }
    for (int e = tid; e < C_P * C_P; e += 256)
        w2s[e >> 6][e & 63] = g_w2t[e];
    __syncthreads();

    int tl = tid & 15, to = tid >> 4;
    float acc[4][2] = {};
    #pragma unroll
    for (int k = 0; k < C_P; k++) {
        float4 a = *(const float4*)&w2s[k][to * 4];
        float2 b = *(const float2*)&hs[k][tl * 2];
        acc[0][0] += a.x * b.x; acc[0][1] += a.x * b.y;
        acc[1][0] += a.y * b.x; acc[1][1] += a.y * b.y;
        acc[2][0] += a.z * b.x; acc[2][1] += a.z * b.y;
        acc[3][0] += a.w * b.x; acc[3][1] += a.w * b.y;
    }
    float4 bv = *(const float4*)&b2[to * 4];
    float bb[4] = {bv.x, bv.y, bv.z, bv.w};
    #pragma unroll
    for (int i = 0; i < 4; i++) {
        int o = to * 4 + i;
        float2 fv;
        float z0 = acc[i][0] + bb[i];
        float z1 = acc[i][1] + bb[i];
        fv.x = 1.f / (1.f + __expf(-z0));
        fv.y = 1.f / (1.f + __expf(-z1));
        *(float2*)&g_f[(n * C_P + o) * L_LEN + l0 + tl * 2] = fv;
    }
}

// ---------------------------------------------------------------------------
// f2bf: transpose f to [n*l][k] fp16 hi/lo + per-position x2
// ---------------------------------------------------------------------------
__global__ void __launch_bounds__(512) f2bf_kernel() {
    int n = blockIdx.x;
    int l = threadIdx.x;
    float s = 0.f;
    #pragma unroll 8
    for (int u = 0; u < 8; u++) {
        uint32_t hw[4], lw[4];
        #pragma unroll
        for (int j = 0; j < 4; j++) {
            float v0 = g_f[(n * C_P + u * 8 + j * 2)     * L_LEN + l];
            float v1 = g_f[(n * C_P + u * 8 + j * 2 + 1) * L_LEN + l];
            s = fmaf(v0, v0, s);
            s = fmaf(v1, v1, s);
            __half h0 = __float2half_rn(v0), h1 = __float2half_rn(v1);
            float r0 = v0 - __half2float(h0), r1 = v1 - __half2float(h1);
            hw[j] = (uint32_t)__half_as_ushort(h0) | ((uint32_t)__half_as_ushort(h1) << 16);
            lw[j] = pack_half2(r0, r1);
        }
        g_fh[(n * L_LEN + l) * 8 + u] = make_uint4(hw[0], hw[1], hw[2], hw[3]);
        g_fl[(n * L_LEN + l) * 8 + u] = make_uint4(lw[0], lw[1], lw[2], lw[3]);
    }
    g_x2[n * L_LEN + l] = s;
}

// ---------------------------------------------------------------------------
// l2min via mma.sync (HMMA): split-fp16 GEMM (pH·fH + pH·fL + pL·fH) + min
// grid (16, 32), 256 threads = 8 warps; block tile 128p x 128l, K=64
// warp tile 32p x 64l; 4 l-chunks
// SMEM rows padded to 72 halves (144 B) -> conflict-free ldmatrix
// ---------------------------------------------------------------------------
#define ROW_H   72
#define ROW_B   144
#define SM_AH   0
#define SM_AL   18432
#define SM_BH   36864
#define SM_BL   55296
#define SM_X2   73728
#define SM_MINB 74240
#define SM_TOT  75264

__global__ void __launch_bounds__(256, 1) l2min_mma_kernel(float* __restrict__ mind_out) {
    extern __shared__ char smem[];
    uint32_t sb = smem_u32(smem);
    float* x2s  = (float*)(smem + SM_X2);
    float* minb = (float*)(smem + SM_MINB);   // [128][2]

    int tid = threadIdx.x;
    int lane = tid & 31, wid = tid >> 5;
    int warpP = wid & 3, warpL = wid >> 2;    // 4 p-warps x 2 l-warps
    int pt = blockIdx.x, n = blockIdx.y;

    // ---- load A (proto hi/lo) : 128 rows x 64 halves ----
    for (int e = tid; e < 1024; e += 256) {
        int row = e >> 3, u = e & 7;
        int off = row * ROW_B + u * 16;
        *(uint4*)(smem + SM_AH + off) = g_ph[(pt * 128 + row) * 8 + u];
        *(uint4*)(smem + SM_AL + off) = g_pl[(pt * 128 + row) * 8 + u];
    }

    // per-thread ldmatrix address components (halves -> bytes)
    // A: row = warpP*32 + mi*16 + (lane&7) + ((lane>>3)&1)*8 ; col = ks*16 + (lane>>4)*8
    int aRow = warpP * 32 + (lane & 7) + ((lane >> 3) & 1) * 8;
    int aCol = ((lane >> 4) & 1) * 8;
    uint32_t aOff = (uint32_t)(aRow * ROW_B + aCol * 2);
    // B: row(l) = warpL*64 + nj*16 + (lane&7) + ((lane>>4)&1)*8 ; col = ks*16 + ((lane>>3)&1)*8
    int bRow = warpL * 64 + (lane & 7) + ((lane >> 4) & 1) * 8;
    int bCol = ((lane >> 3) & 1) * 8;
    uint32_t bOff = (uint32_t)(bRow * ROW_B + bCol * 2);

    float mind[2][2];
    mind[0][0] = mind[0][1] = mind[1][0] = mind[1][1] = 1e30f;

    for (int lc = 0; lc < 4; lc++) {
        __syncthreads();  // B smem reuse vs previous chunk's ldmatrix
        for (int e = tid; e < 1024; e += 256) {
            int row = e >> 3, u = e & 7;
            int off = row * ROW_B + u * 16;
            int gidx = (n * L_LEN + lc * 128 + row) * 8 + u;
            *(uint4*)(smem + SM_BH + off) = g_fh[gidx];
            *(uint4*)(smem + SM_BL + off) = g_fl[gidx];
        }
        if (tid < 128) x2s[tid] = g_x2[n * L_LEN + lc * 128 + tid];
        __syncthreads();

        float acc[2][8][4];
        #pragma unroll
        for (int mi = 0; mi < 2; mi++)
            #pragma unroll
            for (int ni = 0; ni < 8; ni++)
                #pragma unroll
                for (int q = 0; q < 4; q++) acc[mi][ni][q] = 0.f;

        #pragma unroll
        for (int ks = 0; ks < 4; ks++) {
            uint32_t ah[2][4], al[2][4];
            #pragma unroll
            for (int mi = 0; mi < 2; mi++) {
                uint32_t ao = aOff + mi * 16 * ROW_B + ks * 32;
                ldmx4(ah[mi], sb + SM_AH + ao);
                ldmx4(al[mi], sb + SM_AL + ao);
            }
            uint32_t bh[8][2], bl[8][2];
            #pragma unroll
            for (int nj = 0; nj < 4; nj++) {
                uint32_t bo = bOff + nj * 16 * ROW_B + ks * 32;
                uint32_t t[4];
                ldmx4(t, sb + SM_BH + bo);
                bh[nj * 2][0] = t[0]; bh[nj * 2][1] = t[1];
                bh[nj * 2 + 1][0] = t[2]; bh[nj * 2 + 1][1] = t[3];
                ldmx4(t, sb + SM_BL + bo);
                bl[nj * 2][0] = t[0]; bl[nj * 2][1] = t[1];
                bl[nj * 2 + 1][0] = t[2]; bl[nj * 2 + 1][1] = t[3];
            }
            #pragma unroll
            for (int mi = 0; mi < 2; mi++)
                #pragma unroll
                for (int ni = 0; ni < 8; ni++) {
                    mma16816(acc[mi][ni], ah[mi], bh[ni]);
                    mma16816(acc[mi][ni], ah[mi], bl[ni]);
                    mma16816(acc[mi][ni], al[mi], bh[ni]);
                }
        }

        // fold min_l(x2 - 2*xp) into per-thread row minima
        #pragma unroll
        for (int ni = 0; ni < 8; ni++) {
            float2 xv = *(float2*)&x2s[warpL * 64 + ni * 8 + (lane & 3) * 2];
            #pragma unroll
            for (int mi = 0; mi < 2; mi++) {
                float d0 = fmaf(-2.f, acc[mi][ni][0], xv.x);
                float d1 = fmaf(-2.f, acc[mi][ni][1], xv.y);
                float d2 = fmaf(-2.f, acc[mi][ni][2], xv.x);
                float d3 = fmaf(-2.f, acc[mi][ni][3], xv.y);
                mind[mi][0] = fminf(mind[mi][0], fminf(d0, d1));
                mind[mi][1] = fminf(mind[mi][1], fminf(d2, d3));
            }
        }
    }

    // reduce across the 4 col-lanes of each row group
    #pragma unroll
    for (int mi = 0; mi < 2; mi++)
        #pragma unroll
        for (int rh = 0; rh < 2; rh++) {
            float v = mind[mi][rh];
            v = fminf(v, __shfl_xor_sync(0xffffffffu, v, 1));
            v = fminf(v, __shfl_xor_sync(0xffffffffu, v, 2));
            mind[mi][rh] = v;
        }
    __syncthreads();  // minb may alias nothing, but order vs final read
    if ((lane & 3) == 0) {
        int rbase = warpP * 32 + (lane >> 2);
        minb[(rbase +  0) * 2 + warpL] = mind[0][0];
        minb[(rbase +  8) * 2 + warpL] = mind[0][1];
        minb[(rbase + 16) * 2 + warpL] = mind[1][0];
        minb[(rbase + 24) * 2 + warpL] = mind[1][1];
    }
    __syncthreads();

    if (tid < 128) {
        float m = fminf(minb[tid * 2], minb[tid * 2 + 1]);
        float p2v = g_p2[pt * 128 + tid];
        float d = fmaxf(m + p2v, 0.f);
        int p = pt * 128 + tid;
        if (p < P_NUM) {
            if (mind_out) mind_out[n * P_NUM + p] = d;
            g_act[n * P_NUM + p] = logf((d + 1.f) / (d + EPS));
        }
    }
}

// ---------------------------------------------------------------------------
// logits[n][c] = sum_p act[n][p] * last_w[c][p]
// ---------------------------------------------------------------------------
__global__ void logits_kernel(const float* __restrict__ lw, float* __restrict__ out) {
    int c = blockIdx.x, n = blockIdx.y;
    int tid = threadIdx.x;
    const float* a = &g_act[n * P_NUM];
    const float* w = &lw[c * P_NUM];
    float s = 0.f;
    for (int j = tid; j < P_NUM; j += 64)
        s += a[j] * w[j];
    #pragma unroll
    for (int off = 16; off > 0; off >>= 1)
        s += __shfl_xor_sync(0xffffffffu, s, off);
    __shared__ float red[2];
    if ((tid & 31) == 0) red[tid >> 5] = s;
    __syncthreads();
    if (tid == 0) out[n * N_CLS + c] = red[0] + red[1];
}

// ---------------------------------------------------------------------------
extern "C" void kernel_launch(void* const* d_in, const int* in_sizes, int n_in,
                              void* d_out, int out_size) {
    const float* x     = (const float*)d_in[0];
    const float* W1    = (const float*)d_in[1];
    const float* b1    = (const float*)d_in[2];
    const float* W2    = (const float*)d_in[3];
    const float* b2    = (const float*)d_in[4];
    const float* proto = (const float*)d_in[5];
    const float* lw    = (const float*)d_in[6];
    float* out = (float*)d_out;

    float* mind_out = (out_size >= N_B * N_CLS + N_B * P_NUM)
                          ? out + N_B * N_CLS : nullptr;

    cudaFuncSetAttribute(l2min_mma_kernel,
                         cudaFuncAttributeMaxDynamicSharedMemorySize, SM_TOT);

    prep_kernel<<<256, 256>>>(W1, W2, proto);
    conv1_kernel<<<dim3(L_LEN / 32, N_B), 256>>>(x, b1);
    conv2_kernel<<<dim3(L_LEN / 32, N_B), 256>>>(b2);
    f2bf_kernel<<<N_B, 512>>>();
    l2min_mma_kernel<<<dim3(P_PAD / 128, N_B), 256, SM_TOT>>>(mind_out);
    logits_kernel<<<dim3(N_CLS, N_B), 64>>>(lw, out);
}